// round 2
// baseline (speedup 1.0000x reference)
#include <cuda_runtime.h>
#include <cstdint>
#include <cstddef>

// ---------------------------------------------------------------------------
// MeshGNN: N=50000 nodes, E=600000 edges, IN=16, ED=4, H=128, L=4, OUT=3
// Strategy (round 0): fp32, persistent-CTA fused kernels, weights resident in
// shared memory, register-tiled GEMMs, float4 atomic scatter for aggregation.
// ---------------------------------------------------------------------------

#define N_NODES 50000
#define N_EDGES 600000
#define H 128
#define IN_F 16
#define ED 4
#define KE (H + ED)       // 132
#define N_LAYERS 4
#define N_OUT 3
#define TE 64             // edges per tile (E % TE == 0)
#define TN 32             // nodes per tile

// Scratch (static device globals: allocation-free)
__device__ float g_h[(size_t)N_NODES * H];
__device__ float g_agg[(size_t)N_NODES * H];
__device__ float g_inv[N_NODES];

// ---------------------------------------------------------------------------
// Small helper kernels
// ---------------------------------------------------------------------------

__global__ void zero_agg_kernel() {
    size_t i = (size_t)blockIdx.x * blockDim.x + threadIdx.x;
    const size_t n4 = (size_t)N_NODES * H / 4;
    float4 z = make_float4(0.f, 0.f, 0.f, 0.f);
    for (; i < n4; i += (size_t)gridDim.x * blockDim.x)
        reinterpret_cast<float4*>(g_agg)[i] = z;
}

__global__ void zero_cnt_kernel() {
    int i = blockIdx.x * blockDim.x + threadIdx.x;
    if (i < N_NODES) g_inv[i] = 0.f;
}

__global__ void deg_kernel(const int* __restrict__ dst) {
    int e = blockIdx.x * blockDim.x + threadIdx.x;
    if (e < N_EDGES) atomicAdd(&g_inv[dst[e]], 1.0f);
}

__global__ void inv_kernel() {
    int i = blockIdx.x * blockDim.x + threadIdx.x;
    if (i < N_NODES) g_inv[i] = 1.0f / fmaxf(g_inv[i], 1.0f);
}

// h = relu(x @ lin_in_w + lin_in_b); one block (128 threads) per node
__global__ void lin_in_kernel(const float* __restrict__ x,
                              const float* __restrict__ W,
                              const float* __restrict__ b) {
    __shared__ float sx[IN_F];
    int n = blockIdx.x;
    if (threadIdx.x < IN_F) sx[threadIdx.x] = x[(size_t)n * IN_F + threadIdx.x];
    __syncthreads();
    int c = threadIdx.x;
    float acc = __ldg(&b[c]);
#pragma unroll
    for (int k = 0; k < IN_F; k++)
        acc = fmaf(sx[k], __ldg(&W[k * H + c]), acc);
    g_h[(size_t)n * H + c] = fmaxf(acc, 0.f);
}

// ---------------------------------------------------------------------------
// Fused edge MLP + scatter-add.
// Block: 256 threads = 8 warps. Warp w owns edge rows [w*8, w*8+8) of each
// 64-edge tile: gather -> GEMM1 (K=132) -> relu -> GEMM2 (K=128) -> relu ->
// float4 atomic scatter. Weights resident in smem (loaded once per block).
// Thread (w, lane) computes 8 rows x 4 cols (cols = lane*4..lane*4+3).
// ---------------------------------------------------------------------------
__global__ void __launch_bounds__(256, 1)
edge_kernel(const int* __restrict__ src, const int* __restrict__ dst,
            const float* __restrict__ ea,
            const float* __restrict__ W1, const float* __restrict__ b1,
            const float* __restrict__ W2, const float* __restrict__ b2) {
    extern __shared__ float sm[];
    float* sW1 = sm;              // KE*H   = 16896 floats
    float* sW2 = sW1 + KE * H;    // H*H    = 16384 floats
    float* sA  = sW2 + H * H;     // TE*KE  =  8448 floats
    float* sM  = sA + TE * KE;    // TE*H   =  8192 floats

    for (int i = threadIdx.x; i < KE * H; i += 256) sW1[i] = W1[i];
    for (int i = threadIdx.x; i < H * H; i += 256) sW2[i] = W2[i];

    const int lane = threadIdx.x & 31;
    const int w    = threadIdx.x >> 5;
    float b1v[4], b2v[4];
#pragma unroll
    for (int j = 0; j < 4; j++) {
        b1v[j] = __ldg(&b1[lane * 4 + j]);
        b2v[j] = __ldg(&b2[lane * 4 + j]);
    }
    __syncthreads();

    const int ntiles = N_EDGES / TE;  // 9375 exactly
    for (int t = blockIdx.x; t < ntiles; t += gridDim.x) {
        const int e0 = t * TE + w * 8;

        // ---- gather: 8 edges per warp; lane loads 4 consecutive h channels
#pragma unroll
        for (int i = 0; i < 8; i++) {
            int s = __ldg(&src[e0 + i]);
            float4 v = *reinterpret_cast<const float4*>(
                g_h + (size_t)s * H + lane * 4);
            *reinterpret_cast<float4*>(sA + (w * 8 + i) * KE + lane * 4) = v;
        }
        if (lane < 8) {
            float4 a = *reinterpret_cast<const float4*>(
                ea + (size_t)(e0 + lane) * ED);
            *reinterpret_cast<float4*>(sA + (w * 8 + lane) * KE + H) = a;
        }
        __syncwarp();

        // ---- GEMM1: C1 = relu(A[64x132] @ W1[132x128] + b1)
        float acc[8][4];
#pragma unroll
        for (int i = 0; i < 8; i++) {
            acc[i][0] = b1v[0]; acc[i][1] = b1v[1];
            acc[i][2] = b1v[2]; acc[i][3] = b1v[3];
        }
#pragma unroll 1
        for (int kc = 0; kc < KE; kc += 4) {
            float4 a4[8];
#pragma unroll
            for (int i = 0; i < 8; i++)
                a4[i] = *reinterpret_cast<const float4*>(
                    sA + (w * 8 + i) * KE + kc);  // broadcast LDS.128
#pragma unroll
            for (int kk = 0; kk < 4; kk++) {
                float4 bv = *reinterpret_cast<const float4*>(
                    sW1 + (kc + kk) * H + lane * 4);
#pragma unroll
                for (int i = 0; i < 8; i++) {
                    float a = (kk == 0) ? a4[i].x : (kk == 1) ? a4[i].y
                             : (kk == 2) ? a4[i].z : a4[i].w;
                    acc[i][0] = fmaf(a, bv.x, acc[i][0]);
                    acc[i][1] = fmaf(a, bv.y, acc[i][1]);
                    acc[i][2] = fmaf(a, bv.z, acc[i][2]);
                    acc[i][3] = fmaf(a, bv.w, acc[i][3]);
                }
            }
        }
#pragma unroll
        for (int i = 0; i < 8; i++) {
            float4 r = make_float4(fmaxf(acc[i][0], 0.f), fmaxf(acc[i][1], 0.f),
                                   fmaxf(acc[i][2], 0.f), fmaxf(acc[i][3], 0.f));
            *reinterpret_cast<float4*>(sM + (w * 8 + i) * H + lane * 4) = r;
        }
        __syncwarp();

        // ---- GEMM2: C2 = relu(C1[64x128] @ W2[128x128] + b2)
        float acc2[8][4];
#pragma unroll
        for (int i = 0; i < 8; i++) {
            acc2[i][0] = b2v[0]; acc2[i][1] = b2v[1];
            acc2[i][2] = b2v[2]; acc2[i][3] = b2v[3];
        }
#pragma unroll 1
        for (int kc = 0; kc < H; kc += 4) {
            float4 a4[8];
#pragma unroll
            for (int i = 0; i < 8; i++)
                a4[i] = *reinterpret_cast<const float4*>(
                    sM + (w * 8 + i) * H + kc);
#pragma unroll
            for (int kk = 0; kk < 4; kk++) {
                float4 bv = *reinterpret_cast<const float4*>(
                    sW2 + (kc + kk) * H + lane * 4);
#pragma unroll
                for (int i = 0; i < 8; i++) {
                    float a = (kk == 0) ? a4[i].x : (kk == 1) ? a4[i].y
                             : (kk == 2) ? a4[i].z : a4[i].w;
                    acc2[i][0] = fmaf(a, bv.x, acc2[i][0]);
                    acc2[i][1] = fmaf(a, bv.y, acc2[i][1]);
                    acc2[i][2] = fmaf(a, bv.z, acc2[i][2]);
                    acc2[i][3] = fmaf(a, bv.w, acc2[i][3]);
                }
            }
        }

        // ---- scatter: agg[dst] += relu(C2)  (vector red, sm_90+)
#pragma unroll
        for (int i = 0; i < 8; i++) {
            int d = __ldg(&dst[e0 + i]);
            float4 r = make_float4(fmaxf(acc2[i][0], 0.f), fmaxf(acc2[i][1], 0.f),
                                   fmaxf(acc2[i][2], 0.f), fmaxf(acc2[i][3], 0.f));
#if __CUDA_ARCH__ >= 900
            atomicAdd(reinterpret_cast<float4*>(g_agg + (size_t)d * H + lane * 4), r);
#else
            float* p = g_agg + (size_t)d * H + lane * 4;
            atomicAdd(p + 0, r.x); atomicAdd(p + 1, r.y);
            atomicAdd(p + 2, r.z); atomicAdd(p + 3, r.w);
#endif
        }
        __syncwarp();
    }
}

// ---------------------------------------------------------------------------
// Fused node update: u = relu([h, agg/cnt] @ W1 + b1); u2 = u @ W2 + b2;
// h = relu(u2 + h). All weights (192 KB) resident in smem; persistent CTAs.
// Warp w owns node rows [w*4, w*4+4); thread tile = 4 rows x 4 cols.
// ---------------------------------------------------------------------------
__global__ void __launch_bounds__(256, 1)
node_kernel(const float* __restrict__ W1, const float* __restrict__ b1,
            const float* __restrict__ W2, const float* __restrict__ b2) {
    extern __shared__ float sm[];
    float* sW1 = sm;               // 2H*H = 32768 floats
    float* sW2 = sW1 + 2 * H * H;  // H*H  = 16384 floats
    float* sH  = sW2 + H * H;      // TN*H =  4096 floats
    float* sG  = sH + TN * H;      // TN*H =  4096 floats (then reused as U)

    for (int i = threadIdx.x; i < 2 * H * H; i += 256) sW1[i] = W1[i];
    for (int i = threadIdx.x; i < H * H; i += 256) sW2[i] = W2[i];

    const int lane = threadIdx.x & 31;
    const int w    = threadIdx.x >> 5;
    float b1v[4], b2v[4];
#pragma unroll
    for (int j = 0; j < 4; j++) {
        b1v[j] = __ldg(&b1[lane * 4 + j]);
        b2v[j] = __ldg(&b2[lane * 4 + j]);
    }
    __syncthreads();

    const int ntiles = (N_NODES + TN - 1) / TN;
    for (int t = blockIdx.x; t < ntiles; t += gridDim.x) {
        const int n0 = t * TN + w * 4;

        // load h tile and scaled agg tile
#pragma unroll
        for (int i = 0; i < 4; i++) {
            int n = n0 + i;
            float4 hv = make_float4(0.f, 0.f, 0.f, 0.f);
            float4 gv = make_float4(0.f, 0.f, 0.f, 0.f);
            if (n < N_NODES) {
                hv = *reinterpret_cast<const float4*>(g_h + (size_t)n * H + lane * 4);
                float inv = __ldg(&g_inv[n]);
                float4 g = *reinterpret_cast<const float4*>(g_agg + (size_t)n * H + lane * 4);
                gv = make_float4(g.x * inv, g.y * inv, g.z * inv, g.w * inv);
            }
            *reinterpret_cast<float4*>(sH + (w * 4 + i) * H + lane * 4) = hv;
            *reinterpret_cast<float4*>(sG + (w * 4 + i) * H + lane * 4) = gv;
        }
        __syncwarp();

        // GEMM1 over K=256: first h part (W1 rows 0..127), then agg part
        float acc[4][4];
#pragma unroll
        for (int i = 0; i < 4; i++) {
            acc[i][0] = b1v[0]; acc[i][1] = b1v[1];
            acc[i][2] = b1v[2]; acc[i][3] = b1v[3];
        }
#pragma unroll 1
        for (int kc = 0; kc < H; kc += 4) {
            float4 a4[4];
#pragma unroll
            for (int i = 0; i < 4; i++)
                a4[i] = *reinterpret_cast<const float4*>(sH + (w * 4 + i) * H + kc);
#pragma unroll
            for (int kk = 0; kk < 4; kk++) {
                float4 bv = *reinterpret_cast<const float4*>(sW1 + (kc + kk) * H + lane * 4);
#pragma unroll
                for (int i = 0; i < 4; i++) {
                    float a = (kk == 0) ? a4[i].x : (kk == 1) ? a4[i].y
                             : (kk == 2) ? a4[i].z : a4[i].w;
                    acc[i][0] = fmaf(a, bv.x, acc[i][0]);
                    acc[i][1] = fmaf(a, bv.y, acc[i][1]);
                    acc[i][2] = fmaf(a, bv.z, acc[i][2]);
                    acc[i][3] = fmaf(a, bv.w, acc[i][3]);
                }
            }
        }
#pragma unroll 1
        for (int kc = 0; kc < H; kc += 4) {
            float4 a4[4];
#pragma unroll
            for (int i = 0; i < 4; i++)
                a4[i] = *reinterpret_cast<const float4*>(sG + (w * 4 + i) * H + kc);
#pragma unroll
            for (int kk = 0; kk < 4; kk++) {
                float4 bv = *reinterpret_cast<const float4*>(sW1 + (H + kc + kk) * H + lane * 4);
#pragma unroll
                for (int i = 0; i < 4; i++) {
                    float a = (kk == 0) ? a4[i].x : (kk == 1) ? a4[i].y
                             : (kk == 2) ? a4[i].z : a4[i].w;
                    acc[i][0] = fmaf(a, bv.x, acc[i][0]);
                    acc[i][1] = fmaf(a, bv.y, acc[i][1]);
                    acc[i][2] = fmaf(a, bv.z, acc[i][2]);
                    acc[i][3] = fmaf(a, bv.w, acc[i][3]);
                }
            }
        }
        __syncwarp();  // everyone done reading sG before it becomes U

#pragma unroll
        for (int i = 0; i < 4; i++) {
            float4 u = make_float4(fmaxf(acc[i][0], 0.f), fmaxf(acc[i][1], 0.f),
                                   fmaxf(acc[i][2], 0.f), fmaxf(acc[i][3], 0.f));
            *reinterpret_cast<float4*>(sG + (w * 4 + i) * H + lane * 4) = u;
        }
        __syncwarp();

        // GEMM2: u2 = U @ W2 + b2 (no relu), then h = relu(u2 + h)
        float acc2[4][4];
#pragma unroll
        for (int i = 0; i < 4; i++) {
            acc2[i][0] = b2v[0]; acc2[i][1] = b2v[1];
            acc2[i][2] = b2v[2]; acc2[i][3] = b2v[3];
        }
#pragma unroll 1
        for (int kc = 0; kc < H; kc += 4) {
            float4 a4[4];
#pragma unroll
            for (int i = 0; i < 4; i++)
                a4[i] = *reinterpret_cast<const float4*>(sG + (w * 4 + i) * H + kc);
#pragma unroll
            for (int kk = 0; kk < 4; kk++) {
                float4 bv = *reinterpret_cast<const float4*>(sW2 + (kc + kk) * H + lane * 4);
#pragma unroll
                for (int i = 0; i < 4; i++) {
                    float a = (kk == 0) ? a4[i].x : (kk == 1) ? a4[i].y
                             : (kk == 2) ? a4[i].z : a4[i].w;
                    acc2[i][0] = fmaf(a, bv.x, acc2[i][0]);
                    acc2[i][1] = fmaf(a, bv.y, acc2[i][1]);
                    acc2[i][2] = fmaf(a, bv.z, acc2[i][2]);
                    acc2[i][3] = fmaf(a, bv.w, acc2[i][3]);
                }
            }
        }
#pragma unroll
        for (int i = 0; i < 4; i++) {
            int n = n0 + i;
            if (n < N_NODES) {
                float4 hv = *reinterpret_cast<const float4*>(sH + (w * 4 + i) * H + lane * 4);
                float4 o = make_float4(fmaxf(acc2[i][0] + hv.x, 0.f),
                                       fmaxf(acc2[i][1] + hv.y, 0.f),
                                       fmaxf(acc2[i][2] + hv.z, 0.f),
                                       fmaxf(acc2[i][3] + hv.w, 0.f));
                *reinterpret_cast<float4*>(g_h + (size_t)n * H + lane * 4) = o;
            }
        }
        __syncwarp();
    }
}

// ---------------------------------------------------------------------------
// Head: o = relu(h @ W1 + b1); out = relu(o @ W2 + b2), OUT=3.
// GEMM2 (N=3) done via warp shuffle reduction from registers.
// ---------------------------------------------------------------------------
__global__ void __launch_bounds__(256, 1)
head_kernel(const float* __restrict__ W1, const float* __restrict__ b1,
            const float* __restrict__ W2, const float* __restrict__ b2,
            float* __restrict__ out) {
    extern __shared__ float sm[];
    float* sW1 = sm;               // H*H
    float* sW2 = sW1 + H * H;      // H*N_OUT
    float* sH  = sW2 + H * N_OUT;  // TN*H

    for (int i = threadIdx.x; i < H * H; i += 256) sW1[i] = W1[i];
    for (int i = threadIdx.x; i < H * N_OUT; i += 256) sW2[i] = W2[i];

    const int lane = threadIdx.x & 31;
    const int w    = threadIdx.x >> 5;
    float b1v[4];
#pragma unroll
    for (int j = 0; j < 4; j++) b1v[j] = __ldg(&b1[lane * 4 + j]);
    const float b2v0 = __ldg(&b2[0]), b2v1 = __ldg(&b2[1]), b2v2 = __ldg(&b2[2]);
    __syncthreads();

    const int ntiles = (N_NODES + TN - 1) / TN;
    for (int t = blockIdx.x; t < ntiles; t += gridDim.x) {
        const int n0 = t * TN + w * 4;
#pragma unroll
        for (int i = 0; i < 4; i++) {
            int n = n0 + i;
            float4 hv = make_float4(0.f, 0.f, 0.f, 0.f);
            if (n < N_NODES)
                hv = *reinterpret_cast<const float4*>(g_h + (size_t)n * H + lane * 4);
            *reinterpret_cast<float4*>(sH + (w * 4 + i) * H + lane * 4) = hv;
        }
        __syncwarp();

        float acc[4][4];
#pragma unroll
        for (int i = 0; i < 4; i++) {
            acc[i][0] = b1v[0]; acc[i][1] = b1v[1];
            acc[i][2] = b1v[2]; acc[i][3] = b1v[3];
        }
#pragma unroll 1
        for (int kc = 0; kc < H; kc += 4) {
            float4 a4[4];
#pragma unroll
            for (int i = 0; i < 4; i++)
                a4[i] = *reinterpret_cast<const float4*>(sH + (w * 4 + i) * H + kc);
#pragma unroll
            for (int kk = 0; kk < 4; kk++) {
                float4 bv = *reinterpret_cast<const float4*>(sW1 + (kc + kk) * H + lane * 4);
#pragma unroll
                for (int i = 0; i < 4; i++) {
                    float a = (kk == 0) ? a4[i].x : (kk == 1) ? a4[i].y
                             : (kk == 2) ? a4[i].z : a4[i].w;
                    acc[i][0] = fmaf(a, bv.x, acc[i][0]);
                    acc[i][1] = fmaf(a, bv.y, acc[i][1]);
                    acc[i][2] = fmaf(a, bv.z, acc[i][2]);
                    acc[i][3] = fmaf(a, bv.w, acc[i][3]);
                }
            }
        }

        // out = relu(relu(o) @ W2 + b2) via warp reduction
#pragma unroll
        for (int i = 0; i < 4; i++) {
            float p0 = 0.f, p1 = 0.f, p2 = 0.f;
#pragma unroll
            for (int j = 0; j < 4; j++) {
                float o = fmaxf(acc[i][j], 0.f);
                int kk = lane * 4 + j;
                p0 = fmaf(o, sW2[kk * N_OUT + 0], p0);
                p1 = fmaf(o, sW2[kk * N_OUT + 1], p1);
                p2 = fmaf(o, sW2[kk * N_OUT + 2], p2);
            }
#pragma unroll
            for (int off = 16; off > 0; off >>= 1) {
                p0 += __shfl_xor_sync(0xffffffffu, p0, off);
                p1 += __shfl_xor_sync(0xffffffffu, p1, off);
                p2 += __shfl_xor_sync(0xffffffffu, p2, off);
            }
            int n = n0 + i;
            if (lane == 0 && n < N_NODES) {
                out[(size_t)n * N_OUT + 0] = fmaxf(p0 + b2v0, 0.f);
                out[(size_t)n * N_OUT + 1] = fmaxf(p1 + b2v1, 0.f);
                out[(size_t)n * N_OUT + 2] = fmaxf(p2 + b2v2, 0.f);
            }
        }
        __syncwarp();
    }
}

// ---------------------------------------------------------------------------
// Launch
// ---------------------------------------------------------------------------
extern "C" void kernel_launch(void* const* d_in, const int* in_sizes, int n_in,
                              void* d_out, int out_size) {
    const float* x       = (const float*)d_in[0];
    const int*   ei      = (const int*)d_in[1];
    const float* ea      = (const float*)d_in[2];
    const float* lin_w   = (const float*)d_in[3];
    const float* lin_b   = (const float*)d_in[4];
    const float* msg_w1  = (const float*)d_in[5];
    const float* msg_b1  = (const float*)d_in[6];
    const float* msg_w2  = (const float*)d_in[7];
    const float* msg_b2  = (const float*)d_in[8];
    const float* upd_w1  = (const float*)d_in[9];
    const float* upd_b1  = (const float*)d_in[10];
    const float* upd_w2  = (const float*)d_in[11];
    const float* upd_b2  = (const float*)d_in[12];
    const float* head_w1 = (const float*)d_in[13];
    const float* head_b1 = (const float*)d_in[14];
    const float* head_w2 = (const float*)d_in[15];
    const float* head_b2 = (const float*)d_in[16];
    float* out = (float*)d_out;

    const int* src = ei;
    const int* dst = ei + N_EDGES;

    int sm_count = 148;
    cudaDeviceGetAttribute(&sm_count, cudaDevAttrMultiProcessorCount, 0);

    const size_t smE  = (size_t)(KE * H + H * H + TE * KE + TE * H) * sizeof(float);  // ~195 KB
    const size_t smN  = (size_t)(2 * H * H + H * H + 2 * TN * H) * sizeof(float);     // ~224 KB
    const size_t smHd = (size_t)(H * H + H * N_OUT + TN * H) * sizeof(float);         // ~82 KB
    cudaFuncSetAttribute(edge_kernel, cudaFuncAttributeMaxDynamicSharedMemorySize, (int)smE);
    cudaFuncSetAttribute(node_kernel, cudaFuncAttributeMaxDynamicSharedMemorySize, (int)smN);
    cudaFuncSetAttribute(head_kernel, cudaFuncAttributeMaxDynamicSharedMemorySize, (int)smHd);

    zero_cnt_kernel<<<(N_NODES + 255) / 256, 256>>>();
    deg_kernel<<<(N_EDGES + 255) / 256, 256>>>(dst);
    inv_kernel<<<(N_NODES + 255) / 256, 256>>>();
    lin_in_kernel<<<N_NODES, H>>>(x, lin_w, lin_b);

    for (int l = 0; l < N_LAYERS; l++) {
        zero_agg_kernel<<<1024, 256>>>();
        edge_kernel<<<sm_count, 256, smE>>>(
            src, dst, ea,
            msg_w1 + (size_t)l * KE * H, msg_b1 + (size_t)l * H,
            msg_w2 + (size_t)l * H * H, msg_b2 + (size_t)l * H);
        node_kernel<<<sm_count, 256, smN>>>(
            upd_w1 + (size_t)l * 2 * H * H, upd_b1 + (size_t)l * H,
            upd_w2 + (size_t)l * H * H, upd_b2 + (size_t)l * H);
    }

    head_kernel<<<2 * sm_count, 256, smHd>>>(head_w1, head_b1, head_w2, head_b2, out);
}